// round 4
// baseline (speedup 1.0000x reference)
#include <cuda_runtime.h>
#include <math.h>

// Problem constants (from reference: B=4, T=4096, D=1024, H=4*D, 4 experts)
#define T_TOT 16384
#define DDIM  1024
#define HDIM  4096
#define NEXP  4

#define BM 64
#define BN 64
#define BK 16

// Scratch (allocation-free rule: __device__ globals)
__device__ int   g_counts[NEXP];
__device__ int   g_perm[NEXP * T_TOT];
__device__ float g_h[(size_t)T_TOT * HDIM];   // 256 MB hidden activations

// ---------------------------------------------------------------------------
// Expert grouping
// ---------------------------------------------------------------------------
__global__ void k_init_counts() {
    if (threadIdx.x < NEXP) g_counts[threadIdx.x] = 0;
}

__global__ void k_scatter(const int* __restrict__ mask) {
    int t = blockIdx.x * blockDim.x + threadIdx.x;
    if (t < T_TOT) {
        int e = mask[t];
        int pos = atomicAdd(&g_counts[e], 1);
        g_perm[e * T_TOT + pos] = t;
    }
}

// ---------------------------------------------------------------------------
// GEMM1: h[tok, j] = gelu( sum_{k<d_in} x[tok,k] * W1[j,k] + b1[j] ), j < d_hid
// Grouped by expert; rows gathered via g_perm.
// ---------------------------------------------------------------------------
__device__ __forceinline__ float gelu_exact(float v) {
    return 0.5f * v * (1.0f + erff(v * 0.70710678118654752f));
}

__global__ __launch_bounds__(256) void k_gemm1(const float* __restrict__ x,
                                               const float* __restrict__ W1,
                                               const float* __restrict__ b1) {
    const int m = blockIdx.z;
    const int count = g_counts[m];
    const int row0 = blockIdx.y * BM;
    if (row0 >= count) return;
    const int dhid = HDIM >> (NEXP - 1 - m);
    const int col0 = blockIdx.x * BN;
    if (col0 >= dhid) return;
    const int din = DDIM >> (NEXP - 1 - m);

    __shared__ __align__(16) float As[BK][BM + 4];
    __shared__ __align__(16) float Bs[BK][BN + 4];

    const int tid  = threadIdx.x;
    const int lrow = tid >> 2;          // 0..63  (tile row this thread loads)
    const int lk4  = (tid & 3) * 4;     // 0,4,8,12

    const int arow = row0 + lrow;
    const bool avalid = (arow < count);
    const int tok_ld = avalid ? g_perm[m * T_TOT + arow] : 0;
    const float* aptr = x + (size_t)tok_ld * DDIM;
    const float* bptr = W1 + (size_t)(col0 + lrow) * DDIM;   // brow < dhid (64-aligned)

    const int tx = tid & 15, ty = tid >> 4;
    float acc[4][4] = {};

    for (int k0 = 0; k0 < din; k0 += BK) {
        float4 av = avalid ? *(const float4*)(aptr + k0 + lk4)
                           : make_float4(0.f, 0.f, 0.f, 0.f);
        float4 bv = *(const float4*)(bptr + k0 + lk4);
        As[lk4 + 0][lrow] = av.x; As[lk4 + 1][lrow] = av.y;
        As[lk4 + 2][lrow] = av.z; As[lk4 + 3][lrow] = av.w;
        Bs[lk4 + 0][lrow] = bv.x; Bs[lk4 + 1][lrow] = bv.y;
        Bs[lk4 + 2][lrow] = bv.z; Bs[lk4 + 3][lrow] = bv.w;
        __syncthreads();
#pragma unroll
        for (int k = 0; k < BK; k++) {
            float4 a = *(const float4*)&As[k][ty * 4];
            float4 b = *(const float4*)&Bs[k][tx * 4];
            acc[0][0] += a.x * b.x; acc[0][1] += a.x * b.y; acc[0][2] += a.x * b.z; acc[0][3] += a.x * b.w;
            acc[1][0] += a.y * b.x; acc[1][1] += a.y * b.y; acc[1][2] += a.y * b.z; acc[1][3] += a.y * b.w;
            acc[2][0] += a.z * b.x; acc[2][1] += a.z * b.y; acc[2][2] += a.z * b.z; acc[2][3] += a.z * b.w;
            acc[3][0] += a.w * b.x; acc[3][1] += a.w * b.y; acc[3][2] += a.w * b.z; acc[3][3] += a.w * b.w;
        }
        __syncthreads();
    }

#pragma unroll
    for (int r = 0; r < 4; r++) {
        int grow = row0 + ty * 4 + r;
        if (grow < count) {
            int tok = g_perm[m * T_TOT + grow];
            float* hrow = g_h + (size_t)tok * HDIM;
#pragma unroll
            for (int c = 0; c < 4; c++) {
                int j = col0 + tx * 4 + c;
                hrow[j] = gelu_exact(acc[r][c] + b1[j]);
            }
        }
    }
}

// ---------------------------------------------------------------------------
// GEMM2: out[tok, d] = sum_{k<d_hid} h[tok,k] * W2[d,k] + b2[d]
// ---------------------------------------------------------------------------
__global__ __launch_bounds__(256) void k_gemm2(const float* __restrict__ W2,
                                               const float* __restrict__ b2,
                                               float* __restrict__ out) {
    const int m = blockIdx.z;
    const int count = g_counts[m];
    const int row0 = blockIdx.y * BM;
    if (row0 >= count) return;
    const int col0 = blockIdx.x * BN;      // over D=1024, always valid
    const int dhid = HDIM >> (NEXP - 1 - m);

    __shared__ __align__(16) float As[BK][BM + 4];
    __shared__ __align__(16) float Bs[BK][BN + 4];

    const int tid  = threadIdx.x;
    const int lrow = tid >> 2;
    const int lk4  = (tid & 3) * 4;

    const int arow = row0 + lrow;
    const bool avalid = (arow < count);
    const int tok_ld = avalid ? g_perm[m * T_TOT + arow] : 0;
    const float* aptr = g_h + (size_t)tok_ld * HDIM;
    const float* bptr = W2 + (size_t)(col0 + lrow) * HDIM;

    const int tx = tid & 15, ty = tid >> 4;
    float acc[4][4] = {};

    for (int k0 = 0; k0 < dhid; k0 += BK) {
        float4 av = avalid ? *(const float4*)(aptr + k0 + lk4)
                           : make_float4(0.f, 0.f, 0.f, 0.f);
        float4 bv = *(const float4*)(bptr + k0 + lk4);
        As[lk4 + 0][lrow] = av.x; As[lk4 + 1][lrow] = av.y;
        As[lk4 + 2][lrow] = av.z; As[lk4 + 3][lrow] = av.w;
        Bs[lk4 + 0][lrow] = bv.x; Bs[lk4 + 1][lrow] = bv.y;
        Bs[lk4 + 2][lrow] = bv.z; Bs[lk4 + 3][lrow] = bv.w;
        __syncthreads();
#pragma unroll
        for (int k = 0; k < BK; k++) {
            float4 a = *(const float4*)&As[k][ty * 4];
            float4 b = *(const float4*)&Bs[k][tx * 4];
            acc[0][0] += a.x * b.x; acc[0][1] += a.x * b.y; acc[0][2] += a.x * b.z; acc[0][3] += a.x * b.w;
            acc[1][0] += a.y * b.x; acc[1][1] += a.y * b.y; acc[1][2] += a.y * b.z; acc[1][3] += a.y * b.w;
            acc[2][0] += a.z * b.x; acc[2][1] += a.z * b.y; acc[2][2] += a.z * b.z; acc[2][3] += a.z * b.w;
            acc[3][0] += a.w * b.x; acc[3][1] += a.w * b.y; acc[3][2] += a.w * b.z; acc[3][3] += a.w * b.w;
        }
        __syncthreads();
    }

#pragma unroll
    for (int r = 0; r < 4; r++) {
        int grow = row0 + ty * 4 + r;
        if (grow < count) {
            int tok = g_perm[m * T_TOT + grow];
            float* orow = out + (size_t)tok * DDIM;
#pragma unroll
            for (int c = 0; c < 4; c++) {
                int d = col0 + tx * 4 + c;
                orow[d] = acc[r][c] + b2[d];
            }
        }
    }
}

// ---------------------------------------------------------------------------
// Launch
// inputs: 0:x [B,T,D] f32, 1:token_mask [B,T] i32, 2:W1 [H,D] f32,
//         3:b1 [H] f32, 4:W2 [D,H] f32, 5:b2 [D] f32 ; out: [B,T,D] f32
// ---------------------------------------------------------------------------
extern "C" void kernel_launch(void* const* d_in, const int* in_sizes, int n_in,
                              void* d_out, int out_size) {
    const float* x    = (const float*)d_in[0];
    const int*   mask = (const int*)  d_in[1];
    const float* W1   = (const float*)d_in[2];
    const float* b1   = (const float*)d_in[3];
    const float* W2   = (const float*)d_in[4];
    const float* b2   = (const float*)d_in[5];
    float* out = (float*)d_out;

    k_init_counts<<<1, 32>>>();
    k_scatter<<<(T_TOT + 255) / 256, 256>>>(mask);

    // GEMM1: N-tiles up to HDIM/BN = 64, M-tiles 256, 4 experts (most exit early)
    dim3 g1(HDIM / BN, T_TOT / BM, NEXP);
    k_gemm1<<<g1, 256>>>(x, W1, b1);

    // GEMM2: N = DDIM -> 16 tiles
    dim3 g2(DDIM / BN, T_TOT / BM, NEXP);
    k_gemm2<<<g2, 256>>>(W2, b2, out);
}

// round 5
// speedup vs baseline: 1.0582x; 1.0582x over previous
#include <cuda_runtime.h>
#include <math.h>

// Problem constants (from reference: B=4, T=4096, D=1024, H=4*D, 4 experts)
#define T_TOT 16384
#define DDIM  1024
#define HDIM  4096
#define NEXP  4

#define BM 64
#define BN 64
#define BK 16

// Scratch (allocation-free rule: __device__ globals)
__device__ int   g_counts[NEXP];
__device__ int   g_perm[NEXP * T_TOT];
__device__ float g_h[(size_t)T_TOT * HDIM];   // 256 MB hidden activations

// ---------------------------------------------------------------------------
// Expert grouping
// ---------------------------------------------------------------------------
__global__ void k_init_counts() {
    if (threadIdx.x < NEXP) g_counts[threadIdx.x] = 0;
}

__global__ void k_scatter(const int* __restrict__ mask) {
    int t = blockIdx.x * blockDim.x + threadIdx.x;
    if (t < T_TOT) {
        int e = mask[t];
        int pos = atomicAdd(&g_counts[e], 1);
        g_perm[e * T_TOT + pos] = t;
    }
}

// ---------------------------------------------------------------------------
// GEMM1: h[tok, j] = gelu( sum_{k<d_in} x[tok,k] * W1[j,k] + b1[j] ), j < d_hid
// Grouped by expert; rows gathered via g_perm.
// ---------------------------------------------------------------------------
__device__ __forceinline__ float gelu_exact(float v) {
    return 0.5f * v * (1.0f + erff(v * 0.70710678118654752f));
}

__global__ __launch_bounds__(256) void k_gemm1(const float* __restrict__ x,
                                               const float* __restrict__ W1,
                                               const float* __restrict__ b1) {
    const int m = blockIdx.z;
    const int count = g_counts[m];
    const int row0 = blockIdx.y * BM;
    if (row0 >= count) return;
    const int dhid = HDIM >> (NEXP - 1 - m);
    const int col0 = blockIdx.x * BN;
    if (col0 >= dhid) return;
    const int din = DDIM >> (NEXP - 1 - m);

    __shared__ __align__(16) float As[BK][BM + 4];
    __shared__ __align__(16) float Bs[BK][BN + 4];

    const int tid  = threadIdx.x;
    const int lrow = tid >> 2;          // 0..63  (tile row this thread loads)
    const int lk4  = (tid & 3) * 4;     // 0,4,8,12

    const int arow = row0 + lrow;
    const bool avalid = (arow < count);
    const int tok_ld = avalid ? g_perm[m * T_TOT + arow] : 0;
    const float* aptr = x + (size_t)tok_ld * DDIM;
    const float* bptr = W1 + (size_t)(col0 + lrow) * DDIM;   // brow < dhid (64-aligned)

    const int tx = tid & 15, ty = tid >> 4;
    float acc[4][4] = {};

    for (int k0 = 0; k0 < din; k0 += BK) {
        float4 av = avalid ? *(const float4*)(aptr + k0 + lk4)
                           : make_float4(0.f, 0.f, 0.f, 0.f);
        float4 bv = *(const float4*)(bptr + k0 + lk4);
        As[lk4 + 0][lrow] = av.x; As[lk4 + 1][lrow] = av.y;
        As[lk4 + 2][lrow] = av.z; As[lk4 + 3][lrow] = av.w;
        Bs[lk4 + 0][lrow] = bv.x; Bs[lk4 + 1][lrow] = bv.y;
        Bs[lk4 + 2][lrow] = bv.z; Bs[lk4 + 3][lrow] = bv.w;
        __syncthreads();
#pragma unroll
        for (int k = 0; k < BK; k++) {
            float4 a = *(const float4*)&As[k][ty * 4];
            float4 b = *(const float4*)&Bs[k][tx * 4];
            acc[0][0] += a.x * b.x; acc[0][1] += a.x * b.y; acc[0][2] += a.x * b.z; acc[0][3] += a.x * b.w;
            acc[1][0] += a.y * b.x; acc[1][1] += a.y * b.y; acc[1][2] += a.y * b.z; acc[1][3] += a.y * b.w;
            acc[2][0] += a.z * b.x; acc[2][1] += a.z * b.y; acc[2][2] += a.z * b.z; acc[2][3] += a.z * b.w;
            acc[3][0] += a.w * b.x; acc[3][1] += a.w * b.y; acc[3][2] += a.w * b.z; acc[3][3] += a.w * b.w;
        }
        __syncthreads();
    }

#pragma unroll
    for (int r = 0; r < 4; r++) {
        int grow = row0 + ty * 4 + r;
        if (grow < count) {
            int tok = g_perm[m * T_TOT + grow];
            float* hrow = g_h + (size_t)tok * HDIM;
#pragma unroll
            for (int c = 0; c < 4; c++) {
                int j = col0 + tx * 4 + c;
                hrow[j] = gelu_exact(acc[r][c] + b1[j]);
            }
        }
    }
}

// ---------------------------------------------------------------------------
// GEMM2: out[tok, d] = sum_{k<d_hid} h[tok,k] * W2[d,k] + b2[d]
// ---------------------------------------------------------------------------
__global__ __launch_bounds__(256) void k_gemm2(const float* __restrict__ W2,
                                               const float* __restrict__ b2,
                                               float* __restrict__ out) {
    const int m = blockIdx.z;
    const int count = g_counts[m];
    const int row0 = blockIdx.y * BM;
    if (row0 >= count) return;
    const int col0 = blockIdx.x * BN;      // over D=1024, always valid
    const int dhid = HDIM >> (NEXP - 1 - m);

    __shared__ __align__(16) float As[BK][BM + 4];
    __shared__ __align__(16) float Bs[BK][BN + 4];

    const int tid  = threadIdx.x;
    const int lrow = tid >> 2;
    const int lk4  = (tid & 3) * 4;

    const int arow = row0 + lrow;
    const bool avalid = (arow < count);
    const int tok_ld = avalid ? g_perm[m * T_TOT + arow] : 0;
    const float* aptr = g_h + (size_t)tok_ld * HDIM;
    const float* bptr = W2 + (size_t)(col0 + lrow) * HDIM;

    const int tx = tid & 15, ty = tid >> 4;
    float acc[4][4] = {};

    for (int k0 = 0; k0 < dhid; k0 += BK) {
        float4 av = avalid ? *(const float4*)(aptr + k0 + lk4)
                           : make_float4(0.f, 0.f, 0.f, 0.f);
        float4 bv = *(const float4*)(bptr + k0 + lk4);
        As[lk4 + 0][lrow] = av.x; As[lk4 + 1][lrow] = av.y;
        As[lk4 + 2][lrow] = av.z; As[lk4 + 3][lrow] = av.w;
        Bs[lk4 + 0][lrow] = bv.x; Bs[lk4 + 1][lrow] = bv.y;
        Bs[lk4 + 2][lrow] = bv.z; Bs[lk4 + 3][lrow] = bv.w;
        __syncthreads();
#pragma unroll
        for (int k = 0; k < BK; k++) {
            float4 a = *(const float4*)&As[k][ty * 4];
            float4 b = *(const float4*)&Bs[k][tx * 4];
            acc[0][0] += a.x * b.x; acc[0][1] += a.x * b.y; acc[0][2] += a.x * b.z; acc[0][3] += a.x * b.w;
            acc[1][0] += a.y * b.x; acc[1][1] += a.y * b.y; acc[1][2] += a.y * b.z; acc[1][3] += a.y * b.w;
            acc[2][0] += a.z * b.x; acc[2][1] += a.z * b.y; acc[2][2] += a.z * b.z; acc[2][3] += a.z * b.w;
            acc[3][0] += a.w * b.x; acc[3][1] += a.w * b.y; acc[3][2] += a.w * b.z; acc[3][3] += a.w * b.w;
        }
        __syncthreads();
    }

#pragma unroll
    for (int r = 0; r < 4; r++) {
        int grow = row0 + ty * 4 + r;
        if (grow < count) {
            int tok = g_perm[m * T_TOT + grow];
            float* orow = out + (size_t)tok * DDIM;
#pragma unroll
            for (int c = 0; c < 4; c++) {
                int d = col0 + tx * 4 + c;
                orow[d] = acc[r][c] + b2[d];
            }
        }
    }
}

// ---------------------------------------------------------------------------
// Launch
// inputs: 0:x [B,T,D] f32, 1:token_mask [B,T] i32, 2:W1 [H,D] f32,
//         3:b1 [H] f32, 4:W2 [D,H] f32, 5:b2 [D] f32 ; out: [B,T,D] f32
// ---------------------------------------------------------------------------
extern "C" void kernel_launch(void* const* d_in, const int* in_sizes, int n_in,
                              void* d_out, int out_size) {
    const float* x    = (const float*)d_in[0];
    const int*   mask = (const int*)  d_in[1];
    const float* W1   = (const float*)d_in[2];
    const float* b1   = (const float*)d_in[3];
    const float* W2   = (const float*)d_in[4];
    const float* b2   = (const float*)d_in[5];
    float* out = (float*)d_out;

    k_init_counts<<<1, 32>>>();
    k_scatter<<<(T_TOT + 255) / 256, 256>>>(mask);

    // GEMM1: N-tiles up to HDIM/BN = 64, M-tiles 256, 4 experts (most exit early)
    dim3 g1(HDIM / BN, T_TOT / BM, NEXP);
    k_gemm1<<<g1, 256>>>(x, W1, b1);

    // GEMM2: N = DDIM -> 16 tiles
    dim3 g2(DDIM / BN, T_TOT / BM, NEXP);
    k_gemm2<<<g2, 256>>>(W2, b2, out);
}